// round 1
// baseline (speedup 1.0000x reference)
#include <cuda_runtime.h>
#include <math.h>

// Problem constants
#define S_LEN   2048
#define BATCH   2
#define DMODEL  1024
#define NHEADS  16
#define DHEAD   64
#define CLEN    16
#define BHT     32          // BATCH * NHEADS
#define MROWS   4096        // S_LEN * BATCH
#define NCH     32          // number of scan chunks
#define CHLEN   64          // chunk length (NCH*CHLEN == S_LEN)

// Scratch (device globals -- no allocation allowed)
__device__ float g_Q[MROWS * DMODEL];
__device__ float g_K[MROWS * DMODEL];
__device__ float g_V[MROWS * DMODEL];
__device__ float g_O[MROWS * DMODEL];
__device__ float g_Wt[BHT * S_LEN * CLEN];        // logits, then w=exp(logits-max), layout [g][s][c]
__device__ float g_Lmax[BHT * CLEN];
__device__ float g_Psum[BHT * NCH * CLEN * 128];  // per-chunk sums of w*kv, layout [g][chunk][c][d]
__device__ float g_Pden[BHT * NCH * CLEN];        // per-chunk sums of w

// ---------------------------------------------------------------------------
// SGEMM (NT): Out[m][n] = (sum_k A[m][k] * W[n][k] + bias[n]) * colscale(n)
// A: 4096x1024 row-major, W: 1024x1024 row-major (K contiguous).
// mode 0 -> Out=g_Q (apply 1/(8*exp(beta[h])) column scale)
// mode 1 -> Out=g_K, mode 2 -> Out=g_V, mode 3 -> A=g_O, Out=param (d_out)
// BM=BN=128, BK=8, 256 threads, 8x8 microtile.
// ---------------------------------------------------------------------------
__global__ __launch_bounds__(256)
void sgemm_nt(const float* __restrict__ Aopt, const float* __restrict__ W,
              const float* __restrict__ bias, float* __restrict__ Oopt,
              const float* __restrict__ beta, int mode)
{
    const float* A = (mode == 3) ? g_O : Aopt;
    float* Out = (mode == 0) ? g_Q : (mode == 1) ? g_K : (mode == 2) ? g_V : Oopt;

    __shared__ float As[8][128];
    __shared__ float Bs[8][128];

    const int tid = threadIdx.x;
    const int bm = blockIdx.y, bn = blockIdx.x;
    const int lr = tid >> 1;            // 0..127 tile row for loads
    const int lc = (tid & 1) << 2;      // 0 or 4 (float4 column)
    const float* Ap = A + (size_t)(bm * 128 + lr) * DMODEL + lc;
    const float* Wp = W + (size_t)(bn * 128 + lr) * DMODEL + lc;
    const int ty = tid >> 4, tx = tid & 15;

    float acc[8][8];
#pragma unroll
    for (int i = 0; i < 8; i++)
#pragma unroll
        for (int j = 0; j < 8; j++) acc[i][j] = 0.f;

    for (int k0 = 0; k0 < DMODEL; k0 += 8) {
        float4 av = *(const float4*)(Ap + k0);
        float4 bv = *(const float4*)(Wp + k0);
        As[lc + 0][lr] = av.x; As[lc + 1][lr] = av.y;
        As[lc + 2][lr] = av.z; As[lc + 3][lr] = av.w;
        Bs[lc + 0][lr] = bv.x; Bs[lc + 1][lr] = bv.y;
        Bs[lc + 2][lr] = bv.z; Bs[lc + 3][lr] = bv.w;
        __syncthreads();
#pragma unroll
        for (int kk = 0; kk < 8; kk++) {
            float ra[8], rb[8];
#pragma unroll
            for (int i = 0; i < 8; i++) ra[i] = As[kk][ty * 8 + i];
#pragma unroll
            for (int j = 0; j < 8; j++) rb[j] = Bs[kk][tx * 8 + j];
#pragma unroll
            for (int i = 0; i < 8; i++)
#pragma unroll
                for (int j = 0; j < 8; j++)
                    acc[i][j] = fmaf(ra[i], rb[j], acc[i][j]);
        }
        __syncthreads();
    }

    float colb[8], cols[8];
#pragma unroll
    for (int j = 0; j < 8; j++) {
        int n = bn * 128 + tx * 8 + j;
        colb[j] = bias[n];
        cols[j] = (mode == 0) ? (1.0f / (8.0f * expf(beta[n >> 6]))) : 1.0f;
    }
#pragma unroll
    for (int i = 0; i < 8; i++) {
        int m = bm * 128 + ty * 8 + i;
        float* op = Out + (size_t)m * DMODEL + bn * 128 + tx * 8;
#pragma unroll
        for (int j = 0; j < 8; j++)
            op[j] = (acc[i][j] + colb[j]) * cols[j];
    }
}

// ---------------------------------------------------------------------------
// logits[g][s][c] = sum_d q_c[c][h*64+d] * K[s*B+b][h*64+d]
// grid (S/128, BHT), 128 threads, one s per thread.
// ---------------------------------------------------------------------------
__global__ __launch_bounds__(128)
void k_logits(const float* __restrict__ qc)
{
    int g = blockIdx.y, h = g & 15, b = g >> 4;
    __shared__ float qsh[CLEN * DHEAD];
    for (int i = threadIdx.x; i < CLEN * DHEAD; i += 128)
        qsh[i] = qc[(i >> 6) * DMODEL + h * DHEAD + (i & 63)];
    __syncthreads();

    int s = blockIdx.x * 128 + threadIdx.x;
    int m = s * BATCH + b;
    const float* kr = g_K + (size_t)m * DMODEL + h * DHEAD;
    float acc[CLEN];
#pragma unroll
    for (int c = 0; c < CLEN; c++) acc[c] = 0.f;
    for (int d = 0; d < DHEAD; d += 4) {
        float4 kv = *(const float4*)(kr + d);
#pragma unroll
        for (int c = 0; c < CLEN; c++) {
            acc[c] = fmaf(qsh[c * 64 + d + 0], kv.x, acc[c]);
            acc[c] = fmaf(qsh[c * 64 + d + 1], kv.y, acc[c]);
            acc[c] = fmaf(qsh[c * 64 + d + 2], kv.z, acc[c]);
            acc[c] = fmaf(qsh[c * 64 + d + 3], kv.w, acc[c]);
        }
    }
    float* wp = g_Wt + ((size_t)g * S_LEN + s) * CLEN;
#pragma unroll
    for (int c = 0; c < CLEN; c++) wp[c] = acc[c];
}

// max over s per (g,c). grid = BHT*CLEN blocks, 128 threads.
__global__ __launch_bounds__(128)
void k_max()
{
    int gid = blockIdx.x;
    const float* base = g_Wt + (size_t)(gid >> 4) * S_LEN * CLEN + (gid & 15);
    float mx = -3.0e38f;
    for (int i = threadIdx.x; i < S_LEN; i += 128)
        mx = fmaxf(mx, base[(size_t)i * CLEN]);
    __shared__ float sm[128];
    sm[threadIdx.x] = mx;
    __syncthreads();
    for (int off = 64; off > 0; off >>= 1) {
        if (threadIdx.x < off)
            sm[threadIdx.x] = fmaxf(sm[threadIdx.x], sm[threadIdx.x + off]);
        __syncthreads();
    }
    if (threadIdx.x == 0) g_Lmax[gid] = sm[0];
}

// w = exp(logits - max), in place. 1048576 elements.
__global__ void k_exp()
{
    int idx = blockIdx.x * 256 + threadIdx.x;
    int c = idx & 15;
    int g = idx >> 15;   // 2048*16 = 32768 = 2^15
    g_Wt[idx] = expf(g_Wt[idx] - g_Lmax[g * CLEN + c]);
}

// ---------------------------------------------------------------------------
// Phase A: per-chunk partial sums of w*kv (kv = [k;v], 128 dims) and w.
// grid (NCH, BHT), 128 threads; thread d owns kv-dim d for all 16 c.
// ---------------------------------------------------------------------------
__global__ __launch_bounds__(128)
void k_chunksum()
{
    int g = blockIdx.y, cx = blockIdx.x;
    int b = g >> 4, h = g & 15, d = threadIdx.x;
    __shared__ float wsh[CLEN];
    float acc[CLEN];
#pragma unroll
    for (int c = 0; c < CLEN; c++) acc[c] = 0.f;
    float dacc = 0.f;
    const float* kvbase = (d < 64) ? g_K : g_V;
    const int dd = d & 63;

    for (int sl = 0; sl < CHLEN; sl++) {
        int s = cx * CHLEN + sl;
        int m = s * BATCH + b;
        if (d < CLEN) wsh[d] = g_Wt[((size_t)g * S_LEN + s) * CLEN + d];
        __syncthreads();
        float kv = kvbase[(size_t)m * DMODEL + h * DHEAD + dd];
#pragma unroll
        for (int c = 0; c < CLEN; c++) acc[c] = fmaf(wsh[c], kv, acc[c]);
        if (d < CLEN) dacc += wsh[d];
        __syncthreads();
    }
    float* ps = g_Psum + ((size_t)(g * NCH + cx) * CLEN) * 128;
#pragma unroll
    for (int c = 0; c < CLEN; c++) ps[c * 128 + d] = acc[c];
    if (d < CLEN) g_Pden[(g * NCH + cx) * CLEN + d] = dacc;
}

// ---------------------------------------------------------------------------
// Phase B: seeded inclusive scan fused with attention epilogue.
// grid (NCH, BHT), 128 threads; thread d owns kv-dim d of num[c] for all c.
//   att[c] = (qs . num[c][0:64]) / den[c]   (cross-thread reduce over d<64)
//   p = softmax_c(att);  o[d] = sum_c (p[c]/(den[c])) * num[c][64+d]
// ---------------------------------------------------------------------------
__global__ __launch_bounds__(128)
void k_scan()
{
    int g = blockIdx.y, cx = blockIdx.x;
    int b = g >> 4, h = g & 15, d = threadIdx.x;
    int lane = d & 31, w = d >> 5;

    __shared__ float wsh[CLEN], qsh[DHEAD], att_sh[CLEN], coef_sh[CLEN], sden[CLEN];
    __shared__ float red[CLEN][64];

    float num[CLEN];
#pragma unroll
    for (int c = 0; c < CLEN; c++) num[c] = 0.f;

    // exclusive prefix from earlier chunks' partials
    const float* ps = g_Psum + (size_t)g * NCH * CLEN * 128;
    for (int j = 0; j < cx; j++) {
#pragma unroll
        for (int c = 0; c < CLEN; c++)
            num[c] += ps[((size_t)j * CLEN + c) * 128 + d];
    }
    if (d < CLEN) {
        float t = 0.f;
        for (int j = 0; j < cx; j++) t += g_Pden[(g * NCH + j) * CLEN + d];
        sden[d] = t;
    }
    __syncthreads();

    for (int sl = 0; sl < CHLEN; sl++) {
        int s = cx * CHLEN + sl;
        int m = s * BATCH + b;
        if (d < CLEN)  wsh[d] = g_Wt[((size_t)g * S_LEN + s) * CLEN + d];
        if (d < DHEAD) qsh[d] = g_Q[(size_t)m * DMODEL + h * DHEAD + d];
        float kv = (d < 64) ? g_K[(size_t)m * DMODEL + h * DHEAD + d]
                            : g_V[(size_t)m * DMODEL + h * DHEAD + (d - 64)];
        __syncthreads();

#pragma unroll
        for (int c = 0; c < CLEN; c++) num[c] = fmaf(wsh[c], kv, num[c]);
        if (d < CLEN) sden[d] += wsh[d];

        if (d < 64) {
            float qv = qsh[d];
#pragma unroll
            for (int c = 0; c < CLEN; c++) red[c][d] = qv * num[c];
        }
        __syncthreads();

        // reduce over d<64: warp w handles c = 4w..4w+3
#pragma unroll
        for (int cc = 0; cc < 4; cc++) {
            int c = w * 4 + cc;
            float v = red[c][lane] + red[c][lane + 32];
            v += __shfl_xor_sync(0xffffffffu, v, 16);
            v += __shfl_xor_sync(0xffffffffu, v, 8);
            v += __shfl_xor_sync(0xffffffffu, v, 4);
            v += __shfl_xor_sync(0xffffffffu, v, 2);
            v += __shfl_xor_sync(0xffffffffu, v, 1);
            if (lane == 0) att_sh[c] = v;
        }
        __syncthreads();

        // softmax over C=16 in lanes 0..15 of warp 0
        if (d < CLEN) {
            float a = att_sh[d] / sden[d];
            float mx = a;
            mx = fmaxf(mx, __shfl_xor_sync(0xffffu, mx, 8));
            mx = fmaxf(mx, __shfl_xor_sync(0xffffu, mx, 4));
            mx = fmaxf(mx, __shfl_xor_sync(0xffffu, mx, 2));
            mx = fmaxf(mx, __shfl_xor_sync(0xffffu, mx, 1));
            float p = expf(a - mx);
            float sum = p;
            sum += __shfl_xor_sync(0xffffu, sum, 8);
            sum += __shfl_xor_sync(0xffffu, sum, 4);
            sum += __shfl_xor_sync(0xffffu, sum, 2);
            sum += __shfl_xor_sync(0xffffu, sum, 1);
            coef_sh[d] = p / (sum * sden[d]);
        }
        __syncthreads();

        if (d >= 64) {
            float o = 0.f;
#pragma unroll
            for (int c = 0; c < CLEN; c++) o = fmaf(coef_sh[c], num[c], o);
            g_O[(size_t)m * DMODEL + h * DHEAD + (d - 64)] = o;
        }
        __syncthreads();   // protect wsh/qsh for next iteration
    }
}

// ---------------------------------------------------------------------------
extern "C" void kernel_launch(void* const* d_in, const int* in_sizes, int n_in,
                              void* d_out, int out_size)
{
    const float* x    = (const float*)d_in[0];
    const float* q_c  = (const float*)d_in[1];
    const float* beta = (const float*)d_in[2];
    const float* Wq   = (const float*)d_in[3];
    const float* bq   = (const float*)d_in[4];
    const float* Wk   = (const float*)d_in[5];
    const float* bk   = (const float*)d_in[6];
    const float* Wv   = (const float*)d_in[7];
    const float* bv   = (const float*)d_in[8];
    const float* Wo   = (const float*)d_in[9];
    const float* bo   = (const float*)d_in[10];
    float* out = (float*)d_out;

    dim3 gg(DMODEL / 128, MROWS / 128);
    sgemm_nt<<<gg, 256>>>(x, Wq, bq, nullptr, beta, 0);   // Q (scaled)
    sgemm_nt<<<gg, 256>>>(x, Wk, bk, nullptr, beta, 1);   // K
    sgemm_nt<<<gg, 256>>>(x, Wv, bv, nullptr, beta, 2);   // V

    k_logits<<<dim3(S_LEN / 128, BHT), 128>>>(q_c);
    k_max<<<BHT * CLEN, 128>>>();
    k_exp<<<(BHT * S_LEN * CLEN) / 256, 256>>>();

    k_chunksum<<<dim3(NCH, BHT), 128>>>();
    k_scan<<<dim3(NCH, BHT), 128>>>();

    sgemm_nt<<<gg, 256>>>(nullptr, Wo, bo, out, nullptr, 3);  // output proj
}

// round 5
// speedup vs baseline: 2.1166x; 2.1166x over previous
#include <cuda_runtime.h>
#include <cuda_bf16.h>
#include <math.h>
#include <stdint.h>

// Problem constants
#define S_LEN   2048
#define BATCH   2
#define DMODEL  1024
#define NHEADS  16
#define DHEAD   64
#define CLEN    16
#define BHT     32
#define MROWS   4096
#define NCH     32
#define CHLEN   64

// bf16 split storage offsets (elements)
#define OFF_X   0
#define OFF_W   (MROWS * DMODEL)                 // 4M
#define OFF_O   (OFF_W + 4 * DMODEL * DMODEL)    // 8M
#define BF_TOT  (OFF_O + MROWS * DMODEL)         // 12M

// GEMM smem geometry (bf16 tiles, row padded: 32 bf16 data + pad -> 80 bytes/row)
#define ROWW    20                // words per row (80 bytes)
#define TILEW   (128 * ROWW)      // 2560 words per tile
#define STAGEW  (4 * TILEW)       // 10240 words per stage
#define GSMEM   (2 * STAGEW * 4)  // 81920 bytes

// Scratch (device globals -- no allocation allowed)
__device__ __align__(256) float g_Q[MROWS * DMODEL];
__device__ __align__(256) float g_K[MROWS * DMODEL];
__device__ __align__(256) float g_V[MROWS * DMODEL];
__device__ __align__(256) float g_Wt[BHT * S_LEN * CLEN];
__device__ __align__(256) float g_Lmax[BHT * CLEN];
__device__ __align__(256) float g_Psum[BHT * NCH * CLEN * 128];
__device__ __align__(256) float g_Pden[BHT * NCH * CLEN];
__device__ __align__(256) __nv_bfloat16 g_hi[BF_TOT];
__device__ __align__(256) __nv_bfloat16 g_lo[BF_TOT];

// ---------------------------------------------------------------------------
__device__ __forceinline__ uint32_t smem_u32(const void* p) {
    uint32_t a;
    asm("{ .reg .u64 t; cvta.to.shared.u64 t, %1; cvt.u32.u64 %0, t; }" : "=r"(a) : "l"(p));
    return a;
}
#define CP16(dst, src) \
    asm volatile("cp.async.cg.shared.global [%0], [%1], 16;" :: "r"(dst), "l"(src))
#define CP_COMMIT() asm volatile("cp.async.commit_group;" ::: "memory")
#define CP_WAIT0()  asm volatile("cp.async.wait_group 0;" ::: "memory")
#define CP_WAIT1()  asm volatile("cp.async.wait_group 1;" ::: "memory")

__device__ __forceinline__ void mma16816(float* d, const uint32_t* a, const uint32_t* b)
{
    asm volatile(
        "mma.sync.aligned.m16n8k16.row.col.f32.bf16.bf16.f32 "
        "{%0,%1,%2,%3}, {%4,%5,%6,%7}, {%8,%9}, {%0,%1,%2,%3};"
        : "+f"(d[0]), "+f"(d[1]), "+f"(d[2]), "+f"(d[3])
        : "r"(a[0]), "r"(a[1]), "r"(a[2]), "r"(a[3]), "r"(b[0]), "r"(b[1]));
}

// ---------------------------------------------------------------------------
// Split fp32 -> bf16 hi/lo (sources are harness device pointers only)
// ---------------------------------------------------------------------------
__global__ __launch_bounds__(256)
void k_split(const float* __restrict__ src, int dstoff, int n4)
{
    int i = blockIdx.x * 256 + threadIdx.x;
    if (i >= n4) return;
    float4 a = ((const float4*)src)[i];
    __nv_bfloat16 hx = __float2bfloat16(a.x), hy = __float2bfloat16(a.y);
    __nv_bfloat16 hz = __float2bfloat16(a.z), hw = __float2bfloat16(a.w);
    __nv_bfloat16 lx = __float2bfloat16(a.x - __bfloat162float(hx));
    __nv_bfloat16 ly = __float2bfloat16(a.y - __bfloat162float(hy));
    __nv_bfloat16 lz = __float2bfloat16(a.z - __bfloat162float(hz));
    __nv_bfloat16 lw = __float2bfloat16(a.w - __bfloat162float(hw));
    __nv_bfloat162* hi2 = reinterpret_cast<__nv_bfloat162*>(g_hi + dstoff) + 2 * i;
    __nv_bfloat162* lo2 = reinterpret_cast<__nv_bfloat162*>(g_lo + dstoff) + 2 * i;
    hi2[0] = __halves2bfloat162(hx, hy);
    hi2[1] = __halves2bfloat162(hz, hw);
    lo2[0] = __halves2bfloat162(lx, ly);
    lo2[1] = __halves2bfloat162(lz, lw);
}

// ---------------------------------------------------------------------------
// Tensor-core GEMM via mma.sync (3-term bf16 split).
// Out[m][n] = (sum_k A[m][k]*B[n][k] + bias[n]) * scale(n)
// grid (8, 32), 256 threads, 80KB dyn smem, double-buffered cp.async.
// ---------------------------------------------------------------------------
__global__ __launch_bounds__(256)
void gemm_mma(int aoff, int boff, const float* __restrict__ bias,
              const float* __restrict__ beta, int outsel, float* Outp, int qscale)
{
    extern __shared__ __align__(128) char smem_raw[];
    uint32_t* smw = reinterpret_cast<uint32_t*>(smem_raw);
    const uint32_t sb0 = smem_u32(smem_raw);

    float* Out = (outsel == 0) ? g_Q : (outsel == 1) ? g_K : (outsel == 2) ? g_V : Outp;

    const int tid = threadIdx.x;
    const int bn = blockIdx.x, bm = blockIdx.y;
    const int warp = tid >> 5, lane = tid & 31;
    const int wm = warp & 1, wn = warp >> 1;
    const int g = lane >> 2, tig = lane & 3;

    const char* a_h = (const char*)(g_hi + aoff) + (size_t)(bm * 128) * 2048;
    const char* a_l = (const char*)(g_lo + aoff) + (size_t)(bm * 128) * 2048;
    const char* b_h = (const char*)(g_hi + boff) + (size_t)(bn * 128) * 2048;
    const char* b_l = (const char*)(g_lo + boff) + (size_t)(bn * 128) * 2048;

    float acc[4][4][4];
#pragma unroll
    for (int mi = 0; mi < 4; mi++)
#pragma unroll
        for (int ni = 0; ni < 4; ni++)
#pragma unroll
            for (int r = 0; r < 4; r++) acc[mi][ni][r] = 0.f;

    const int lrow0 = tid >> 2, lseg = tid & 3;

#define LOAD_STAGE(kc, s) do { \
    uint32_t dstb = sb0 + (s) * (STAGEW * 4); \
    size_t kb = (size_t)(kc) * 64; \
    _Pragma("unroll") \
    for (int j = 0; j < 2; j++) { \
        int row = lrow0 + j * 64; \
        uint32_t doff = (uint32_t)row * 80 + lseg * 16; \
        size_t soff = (size_t)row * 2048 + kb + lseg * 16; \
        CP16(dstb + 0                 + doff, a_h + soff); \
        CP16(dstb + (TILEW * 4)       + doff, a_l + soff); \
        CP16(dstb + (2 * TILEW * 4)   + doff, b_h + soff); \
        CP16(dstb + (3 * TILEW * 4)   + doff, b_l + soff); \
    } \
    CP_COMMIT(); } while (0)

    LOAD_STAGE(0, 0);

    for (int kc = 0; kc < 32; kc++) {
        int s = kc & 1;
        if (kc + 1 < 32) { LOAD_STAGE(kc + 1, s ^ 1); CP_WAIT1(); }
        else             { CP_WAIT0(); }
        __syncthreads();

        const uint32_t* Ahw = smw + s * STAGEW;
        const uint32_t* Alw = Ahw + TILEW;
        const uint32_t* Bhw = Ahw + 2 * TILEW;
        const uint32_t* Blw = Ahw + 3 * TILEW;

#pragma unroll
        for (int ks = 0; ks < 2; ks++) {
            uint32_t ah[4][4], al[4][4], bh[4][2], bl[4][2];
#pragma unroll
            for (int mi = 0; mi < 4; mi++) {
                int r0 = (wm * 64 + mi * 16 + g) * ROWW + ks * 8 + tig;
                int r1 = r0 + 8 * ROWW;
                ah[mi][0] = Ahw[r0];     ah[mi][1] = Ahw[r1];
                ah[mi][2] = Ahw[r0 + 4]; ah[mi][3] = Ahw[r1 + 4];
                al[mi][0] = Alw[r0];     al[mi][1] = Alw[r1];
                al[mi][2] = Alw[r0 + 4]; al[mi][3] = Alw[r1 + 4];
            }
#pragma unroll
            for (int ni = 0; ni < 4; ni++) {
                int r0 = (wn * 32 + ni * 8 + g) * ROWW + ks * 8 + tig;
                bh[ni][0] = Bhw[r0]; bh[ni][1] = Bhw[r0 + 4];
                bl[ni][0] = Blw[r0]; bl[ni][1] = Blw[r0 + 4];
            }
#pragma unroll
            for (int mi = 0; mi < 4; mi++)
#pragma unroll
                for (int ni = 0; ni < 4; ni++) {
                    mma16816(acc[mi][ni], ah[mi], bh[ni]);
                    mma16816(acc[mi][ni], ah[mi], bl[ni]);
                    mma16816(acc[mi][ni], al[mi], bh[ni]);
                }
        }
        __syncthreads();
    }
#undef LOAD_STAGE

    const int ncol0 = bn * 128 + wn * 32;
    float sc = qscale ? (1.0f / (8.0f * expf(beta[ncol0 >> 6]))) : 1.0f;
#pragma unroll
    for (int mi = 0; mi < 4; mi++) {
        int m0 = bm * 128 + wm * 64 + mi * 16 + g;
#pragma unroll
        for (int ni = 0; ni < 4; ni++) {
            int n0 = ncol0 + ni * 8 + tig * 2;
            float b0 = bias[n0], b1 = bias[n0 + 1];
            float2 v0, v1;
            v0.x = (acc[mi][ni][0] + b0) * sc;
            v0.y = (acc[mi][ni][1] + b1) * sc;
            v1.x = (acc[mi][ni][2] + b0) * sc;
            v1.y = (acc[mi][ni][3] + b1) * sc;
            *(float2*)(Out + (size_t)m0 * DMODEL + n0) = v0;
            *(float2*)(Out + (size_t)(m0 + 8) * DMODEL + n0) = v1;
        }
    }
}

// ---------------------------------------------------------------------------
// Attention-side kernels
// ---------------------------------------------------------------------------
__global__ __launch_bounds__(128)
void k_logits(const float* __restrict__ qc)
{
    int g = blockIdx.y, h = g & 15, b = g >> 4;
    __shared__ float qsh[CLEN * DHEAD];
    for (int i = threadIdx.x; i < CLEN * DHEAD; i += 128)
        qsh[i] = qc[(i >> 6) * DMODEL + h * DHEAD + (i & 63)];
    __syncthreads();

    int s = blockIdx.x * 128 + threadIdx.x;
    int m = s * BATCH + b;
    const float* kr = g_K + (size_t)m * DMODEL + h * DHEAD;
    float acc[CLEN];
#pragma unroll
    for (int c = 0; c < CLEN; c++) acc[c] = 0.f;
    for (int d = 0; d < DHEAD; d += 4) {
        float4 kv = *(const float4*)(kr + d);
#pragma unroll
        for (int c = 0; c < CLEN; c++) {
            acc[c] = fmaf(qsh[c * 64 + d + 0], kv.x, acc[c]);
            acc[c] = fmaf(qsh[c * 64 + d + 1], kv.y, acc[c]);
            acc[c] = fmaf(qsh[c * 64 + d + 2], kv.z, acc[c]);
            acc[c] = fmaf(qsh[c * 64 + d + 3], kv.w, acc[c]);
        }
    }
    float* wp = g_Wt + ((size_t)g * S_LEN + s) * CLEN;
#pragma unroll
    for (int c = 0; c < CLEN; c++) wp[c] = acc[c];
}

__global__ __launch_bounds__(128)
void k_max()
{
    int gid = blockIdx.x;
    const float* base = g_Wt + (size_t)(gid >> 4) * S_LEN * CLEN + (gid & 15);
    float mx = -3.0e38f;
    for (int i = threadIdx.x; i < S_LEN; i += 128)
        mx = fmaxf(mx, base[(size_t)i * CLEN]);
    __shared__ float sm[128];
    sm[threadIdx.x] = mx;
    __syncthreads();
    for (int off = 64; off > 0; off >>= 1) {
        if (threadIdx.x < off)
            sm[threadIdx.x] = fmaxf(sm[threadIdx.x], sm[threadIdx.x + off]);
        __syncthreads();
    }
    if (threadIdx.x == 0) g_Lmax[gid] = sm[0];
}

__global__ void k_exp()
{
    int idx = blockIdx.x * 256 + threadIdx.x;
    int c = idx & 15;
    int g = idx >> 15;
    g_Wt[idx] = expf(g_Wt[idx] - g_Lmax[g * CLEN + c]);
}

__global__ __launch_bounds__(128)
void k_chunksum()
{
    int g = blockIdx.y, cx = blockIdx.x;
    int b = g >> 4, h = g & 15, d = threadIdx.x;
    __shared__ float wsh[CLEN];
    float acc[CLEN];
#pragma unroll
    for (int c = 0; c < CLEN; c++) acc[c] = 0.f;
    float dacc = 0.f;
    const float* kvbase = (d < 64) ? g_K : g_V;
    const int dd = d & 63;

    for (int sl = 0; sl < CHLEN; sl++) {
        int s = cx * CHLEN + sl;
        int m = s * BATCH + b;
        if (d < CLEN) wsh[d] = g_Wt[((size_t)g * S_LEN + s) * CLEN + d];
        __syncthreads();
        float kv = kvbase[(size_t)m * DMODEL + h * DHEAD + dd];
#pragma unroll
        for (int c = 0; c < CLEN; c++) acc[c] = fmaf(wsh[c], kv, acc[c]);
        if (d < CLEN) dacc += wsh[d];
        __syncthreads();
    }
    float* ps = g_Psum + ((size_t)(g * NCH + cx) * CLEN) * 128;
#pragma unroll
    for (int c = 0; c < CLEN; c++) ps[c * 128 + d] = acc[c];
    if (d < CLEN) g_Pden[(g * NCH + cx) * CLEN + d] = dacc;
}

// Phase B: scan + attention epilogue; writes bf16 hi/lo of O directly.
__global__ __launch_bounds__(128)
void k_scan()
{
    int g = blockIdx.y, cx = blockIdx.x;
    int b = g >> 4, h = g & 15, d = threadIdx.x;
    int lane = d & 31, w = d >> 5;

    __shared__ float wsh[CLEN], qsh[DHEAD], att_sh[CLEN], coef_sh[CLEN], sden[CLEN];
    __shared__ float red[CLEN][64];

    float num[CLEN];
#pragma unroll
    for (int c = 0; c < CLEN; c++) num[c] = 0.f;

    const float* ps = g_Psum + (size_t)g * NCH * CLEN * 128;
    for (int j = 0; j < cx; j++) {
#pragma unroll
        for (int c = 0; c < CLEN; c++)
            num[c] += ps[((size_t)j * CLEN + c) * 128 + d];
    }
    if (d < CLEN) {
        float t = 0.f;
        for (int j = 0; j < cx; j++) t += g_Pden[(g * NCH + j) * CLEN + d];
        sden[d] = t;
    }
    __syncthreads();

    for (int sl = 0; sl < CHLEN; sl++) {
        int s = cx * CHLEN + sl;
        int m = s * BATCH + b;
        if (d < CLEN)  wsh[d] = g_Wt[((size_t)g * S_LEN + s) * CLEN + d];
        if (d < DHEAD) qsh[d] = g_Q[(size_t)m * DMODEL + h * DHEAD + d];
        float kv = (d < 64) ? g_K[(size_t)m * DMODEL + h * DHEAD + d]
                            : g_V[(size_t)m * DMODEL + h * DHEAD + (d - 64)];
        __syncthreads();

#pragma unroll
        for (int c = 0; c < CLEN; c++) num[c] = fmaf(wsh[c], kv, num[c]);
        if (d < CLEN) sden[d] += wsh[d];

        if (d < 64) {
            float qv = qsh[d];
#pragma unroll
            for (int c = 0; c < CLEN; c++) red[c][d] = qv * num[c];
        }
        __syncthreads();

#pragma unroll
        for (int cc = 0; cc < 4; cc++) {
            int c = w * 4 + cc;
            float v = red[c][lane] + red[c][lane + 32];
            v += __shfl_xor_sync(0xffffffffu, v, 16);
            v += __shfl_xor_sync(0xffffffffu, v, 8);
            v += __shfl_xor_sync(0xffffffffu, v, 4);
            v += __shfl_xor_sync(0xffffffffu, v, 2);
            v += __shfl_xor_sync(0xffffffffu, v, 1);
            if (lane == 0) att_sh[c] = v;
        }
        __syncthreads();

        if (d < CLEN) {
            float a = att_sh[d] / sden[d];
            float mx = a;
            mx = fmaxf(mx, __shfl_xor_sync(0xffffu, mx, 8));
            mx = fmaxf(mx, __shfl_xor_sync(0xffffu, mx, 4));
            mx = fmaxf(mx, __shfl_xor_sync(0xffffu, mx, 2));
            mx = fmaxf(mx, __shfl_xor_sync(0xffffu, mx, 1));
            float p = expf(a - mx);
            float sum = p;
            sum += __shfl_xor_sync(0xffffu, sum, 8);
            sum += __shfl_xor_sync(0xffffu, sum, 4);
            sum += __shfl_xor_sync(0xffffu, sum, 2);
            sum += __shfl_xor_sync(0xffffu, sum, 1);
            coef_sh[d] = p / (sum * sden[d]);
        }
        __syncthreads();

        if (d >= 64) {
            float o = 0.f;
#pragma unroll
            for (int c = 0; c < CLEN; c++) o = fmaf(coef_sh[c], num[c], o);
            // fused bf16 split of O (device-side; no host pointer involved)
            __nv_bfloat16 hi = __float2bfloat16(o);
            __nv_bfloat16 lo = __float2bfloat16(o - __bfloat162float(hi));
            size_t idx = (size_t)OFF_O + (size_t)m * DMODEL + h * DHEAD + (d - 64);
            g_hi[idx] = hi;
            g_lo[idx] = lo;
        }
        __syncthreads();
    }
}

// ---------------------------------------------------------------------------
extern "C" void kernel_launch(void* const* d_in, const int* in_sizes, int n_in,
                              void* d_out, int out_size)
{
    const float* x    = (const float*)d_in[0];
    const float* q_c  = (const float*)d_in[1];
    const float* beta = (const float*)d_in[2];
    const float* Wq   = (const float*)d_in[3];
    const float* bq   = (const float*)d_in[4];
    const float* Wk   = (const float*)d_in[5];
    const float* bk   = (const float*)d_in[6];
    const float* Wv   = (const float*)d_in[7];
    const float* bv   = (const float*)d_in[8];
    const float* Wo   = (const float*)d_in[9];
    const float* bo   = (const float*)d_in[10];
    float* out = (float*)d_out;

    static int smem_cfg_done = 0;
    if (!smem_cfg_done) {
        cudaFuncSetAttribute(gemm_mma, cudaFuncAttributeMaxDynamicSharedMemorySize, GSMEM);
        smem_cfg_done = 1;
    }

    const int WN4 = DMODEL * DMODEL / 4;
    const int XN4 = MROWS * DMODEL / 4;

    k_split<<<(XN4 + 255) / 256, 256>>>(x, OFF_X, XN4);
    k_split<<<(WN4 + 255) / 256, 256>>>(Wq, OFF_W + 0 * DMODEL * DMODEL, WN4);
    k_split<<<(WN4 + 255) / 256, 256>>>(Wk, OFF_W + 1 * DMODEL * DMODEL, WN4);
    k_split<<<(WN4 + 255) / 256, 256>>>(Wv, OFF_W + 2 * DMODEL * DMODEL, WN4);
    k_split<<<(WN4 + 255) / 256, 256>>>(Wo, OFF_W + 3 * DMODEL * DMODEL, WN4);

    dim3 gg(DMODEL / 128, MROWS / 128);
    gemm_mma<<<gg, 256, GSMEM>>>(OFF_X, OFF_W + 0 * DMODEL * DMODEL, bq, beta, 0, nullptr, 1);
    gemm_mma<<<gg, 256, GSMEM>>>(OFF_X, OFF_W + 1 * DMODEL * DMODEL, bk, beta, 1, nullptr, 0);
    gemm_mma<<<gg, 256, GSMEM>>>(OFF_X, OFF_W + 2 * DMODEL * DMODEL, bv, beta, 2, nullptr, 0);

    k_logits<<<dim3(S_LEN / 128, BHT), 128>>>(q_c);
    k_max<<<BHT * CLEN, 128>>>();
    k_exp<<<(BHT * S_LEN * CLEN) / 256, 256>>>();
    k_chunksum<<<dim3(NCH, BHT), 128>>>();
    k_scan<<<dim3(NCH, BHT), 128>>>();

    gemm_mma<<<gg, 256, GSMEM>>>(OFF_O, OFF_W + 3 * DMODEL * DMODEL, bo, beta, 3, out, 0);
}